// round 3
// baseline (speedup 1.0000x reference)
#include <cuda_runtime.h>
#include <cuda_bf16.h>
#include <math.h>

// Problem dims (fixed by reference)
#define NB 2
#define CC 8192
#define HID 4096
#define RDIM 512
#define HH 8
#define PH 64           // per-head dim
#define DD 128          // landmark chunks
#define TOPK 16
#define NROWS (NB*CC)   // 16384

// -------- device scratch (no allocations allowed) --------
__device__ float g_scale[NROWS];              // 64 KB
__device__ float g_wt[HID * RDIM];            // 8 MB, W^T with pre_norm_weight folded
__device__ float g_q[NROWS * RDIM];           // 33.5 MB, q_emb

// ============================================================
// Kernel 1: per-row inverse RMS
// ============================================================
__global__ __launch_bounds__(256) void rms_scale_kernel(const float* __restrict__ x) {
    int row = blockIdx.x;
    const float4* xr = (const float4*)(x + (size_t)row * HID);
    float sum = 0.f;
#pragma unroll
    for (int i = 0; i < 4; i++) {
        float4 v = xr[threadIdx.x + i * 256];
        sum += v.x * v.x + v.y * v.y + v.z * v.z + v.w * v.w;
    }
#pragma unroll
    for (int o = 16; o; o >>= 1) sum += __shfl_xor_sync(0xffffffffu, sum, o);
    __shared__ float red[8];
    if ((threadIdx.x & 31) == 0) red[threadIdx.x >> 5] = sum;
    __syncthreads();
    if (threadIdx.x < 8) {
        float s = red[threadIdx.x];
#pragma unroll
        for (int o = 4; o; o >>= 1) s += __shfl_xor_sync(0xffu, s, o);
        if (threadIdx.x == 0)
            g_scale[row] = rsqrtf(s * (1.0f / (float)HID) + 1e-6f);
    }
}

// ============================================================
// Kernel 2: g_wt[j][o] = W[o][j] * pre_norm_weight[j]   (tiled transpose)
// ============================================================
__global__ void prep_w_kernel(const float* __restrict__ W, const float* __restrict__ prew) {
    __shared__ float tile[32][33];
    int jb = blockIdx.x * 32;   // over HID
    int ob = blockIdx.y * 32;   // over RDIM
    int tx = threadIdx.x, ty = threadIdx.y;  // 32 x 8
#pragma unroll
    for (int r = 0; r < 4; r++) {
        int o = ob + ty + r * 8;
        tile[ty + r * 8][tx] = W[(size_t)o * HID + jb + tx];
    }
    __syncthreads();
#pragma unroll
    for (int r = 0; r < 4; r++) {
        int jl = ty + r * 8;
        int j = jb + jl;
        g_wt[(size_t)j * RDIM + ob + tx] = tile[tx][jl] * prew[j];
    }
}

// ============================================================
// Kernel 3: SGEMM  g_q[m][o] = g_scale[m] * sum_j hidden[m][j] * g_wt[j][o]
//   BM=128 BN=64 BK=16, 256 threads, thread tile 8x4
// ============================================================
#define BM 128
#define BN 64
#define BK 16
__global__ __launch_bounds__(256) void gemm_kernel(const float* __restrict__ A) {
    __shared__ __align__(16) float As[BK][BM];
    __shared__ __align__(16) float Bs[BK][BN];
    const int bm = blockIdx.y * BM;
    const int bn = blockIdx.x * BN;
    const int tid = threadIdx.x;
    const int ty = tid >> 4;   // 0..15 (m groups of 8)
    const int tx = tid & 15;   // 0..15 (n groups of 4)

    float acc[8][4];
#pragma unroll
    for (int i = 0; i < 8; i++)
#pragma unroll
        for (int j = 0; j < 4; j++) acc[i][j] = 0.f;

    for (int k0 = 0; k0 < HID; k0 += BK) {
        // load A tile (128x16) transposed into As[k][m]
#pragma unroll
        for (int i = 0; i < 2; i++) {
            int p = tid * 2 + i;      // 0..511
            int r = p >> 2;           // row 0..127
            int c4 = p & 3;           // f4 index within the 16-wide row
            float4 v = *(const float4*)(A + (size_t)(bm + r) * HID + k0 + c4 * 4);
            As[c4 * 4 + 0][r] = v.x;
            As[c4 * 4 + 1][r] = v.y;
            As[c4 * 4 + 2][r] = v.z;
            As[c4 * 4 + 3][r] = v.w;
        }
        // load B tile (16x64)
        {
            int r = tid >> 4;         // 0..15
            int c4 = tid & 15;        // 0..15
            float4 v = *(const float4*)(g_wt + (size_t)(k0 + r) * RDIM + bn + c4 * 4);
            *(float4*)&Bs[r][c4 * 4] = v;
        }
        __syncthreads();
#pragma unroll
        for (int k = 0; k < BK; k++) {
            float4 a03 = *(const float4*)&As[k][ty * 8];
            float4 a47 = *(const float4*)&As[k][ty * 8 + 4];
            float4 bv  = *(const float4*)&Bs[k][tx * 4];
            float a[8] = {a03.x, a03.y, a03.z, a03.w, a47.x, a47.y, a47.z, a47.w};
            float b[4] = {bv.x, bv.y, bv.z, bv.w};
#pragma unroll
            for (int i = 0; i < 8; i++)
#pragma unroll
                for (int j = 0; j < 4; j++) acc[i][j] += a[i] * b[j];
        }
        __syncthreads();
    }
    // epilogue: apply rms scale per row
    int mbase = bm + ty * 8;
    int nbase = bn + tx * 4;
#pragma unroll
    for (int i = 0; i < 8; i++) {
        float s = g_scale[mbase + i];
        float4 o;
        o.x = acc[i][0] * s; o.y = acc[i][1] * s; o.z = acc[i][2] * s; o.w = acc[i][3] * s;
        *(float4*)(g_q + (size_t)(mbase + i) * RDIM + nbase) = o;
    }
}

// ============================================================
// Kernel 4: scores (vs landmarks), causal top-16, index-desc sort,
//           softplus-cumsum weights. One thread per (n,c,h).
// ============================================================
__global__ __launch_bounds__(128) void scores_kernel(const float* __restrict__ lmk,
                                                     float* __restrict__ out) {
    const int n = blockIdx.z;
    const int h = blockIdx.y;
    const int c = blockIdx.x * 128 + threadIdx.x;

    // landmarks for this (n,h): [128 chunks][64] -> 32 KB smem
    __shared__ __align__(16) float4 sL[DD * 16];
    {
        int d = threadIdx.x;  // 0..127
        const float4* src = (const float4*)(lmk + ((size_t)((n * DD + d) * HH + h) << 6));
#pragma unroll
        for (int e = 0; e < 16; e++) sL[d * 16 + e] = src[e];
    }
    __syncthreads();

    // q row (64 floats) in registers
    float4 qv[16];
    const float4* qp = (const float4*)(g_q + ((size_t)(n * CC + c) * RDIM + h * PH));
#pragma unroll
    for (int e = 0; e < 16; e++) qv[e] = qp[e];

    int v = c >> 6;               // visible chunks; c<8192 -> v<=127
    float tv[TOPK];               // ascending values, tv[0] = current min
    int   ti[TOPK];
#pragma unroll
    for (int i = 0; i < TOPK; i++) { tv[i] = -INFINITY; ti[i] = -1; }

    for (int j = 0; j < v; j++) {
        float dot = 0.f;
#pragma unroll
        for (int e = 0; e < 16; e++) {
            float4 l = sL[j * 16 + e];
            dot += qv[e].x * l.x + qv[e].y * l.y + qv[e].z * l.z + qv[e].w * l.w;
        }
        float s = dot * 0.125f;   // / sqrt(64)
        if (s > tv[0]) {          // strict: ties keep earlier index (matches lax.top_k)
            bool done = false;
#pragma unroll
            for (int i = 0; i < TOPK - 1; i++) {
                if (!done) {
                    if (tv[i + 1] < s) { tv[i] = tv[i + 1]; ti[i] = ti[i + 1]; }
                    else               { tv[i] = s; ti[i] = j; done = true; }
                }
            }
            if (!done) { tv[TOPK - 1] = s; ti[TOPK - 1] = j; }
        }
    }

    // sort pairs by index descending (invalid ti=-1 sink to the end)
#pragma unroll
    for (int a = 0; a < TOPK - 1; a++)
#pragma unroll
        for (int b = 0; b < TOPK - 1 - a; b++) {
            if (ti[b] < ti[b + 1]) {
                int   t0 = ti[b]; ti[b] = ti[b + 1]; ti[b + 1] = t0;
                float t1 = tv[b]; tv[b] = tv[b + 1]; tv[b + 1] = t1;
            }
        }

    // softplus(threshold=15) cumsum -> weights
    const size_t IDX_OFF = (size_t)NB * CC * HH * TOPK;  // 2097152
    size_t base = ((size_t)(n * CC + c) * HH + h) << 4;
    float cum = 0.f;
#pragma unroll
    for (int i = 0; i < TOPK; i++) {
        bool valid = ti[i] >= 0;
        float s = valid ? tv[i] : -INFINITY;
        float sp = (s > 15.0f) ? s : log1pf(expf(s));    // s=-inf -> 0
        cum += sp;
        float w = expf(s - cum);                          // -inf -> 0
        out[base + i] = w;
        out[IDX_OFF + base + i] = valid ? (float)ti[i] : 0.0f;
    }
}

// ============================================================
extern "C" void kernel_launch(void* const* d_in, const int* in_sizes, int n_in,
                              void* d_out, int out_size) {
    const float* hidden = (const float*)d_in[0];  // (2, 8192, 4096)
    const float* lmk    = (const float*)d_in[1];  // (2, 128, 8, 64)
    const float* prew   = (const float*)d_in[2];  // (4096,)
    const float* W      = (const float*)d_in[3];  // (512, 4096)
    float* out = (float*)d_out;

    rms_scale_kernel<<<NROWS, 256>>>(hidden);
    prep_w_kernel<<<dim3(HID / 32, RDIM / 32), dim3(32, 8)>>>(W, prew);
    gemm_kernel<<<dim3(RDIM / BN, NROWS / BM), 256>>>(hidden);
    scores_kernel<<<dim3(CC / 128, HH, NB), 128>>>(lmk, out);
}

// round 5
// speedup vs baseline: 2.4100x; 2.4100x over previous
#include <cuda_runtime.h>
#include <cuda_bf16.h>
#include <math.h>
#include <stdint.h>

#define NB 2
#define CC 8192
#define HID 4096
#define RDIM 512
#define HH 8
#define DD 128
#define TOPK 16
#define NROWS (NB*CC)

// -------- device scratch --------
__device__ float g_scale[NROWS];
__device__ __nv_bfloat16 g_ahi[(size_t)NROWS * HID];
__device__ __nv_bfloat16 g_alo[(size_t)NROWS * HID];
__device__ __nv_bfloat16 g_bhi[(size_t)RDIM * HID];
__device__ __nv_bfloat16 g_blo[(size_t)RDIM * HID];
__device__ float g_q[(size_t)NROWS * RDIM];

// -------- helpers --------
__device__ __forceinline__ unsigned long long pk4(float a, float b, float c, float d) {
    return (unsigned long long)__bfloat16_as_ushort(__float2bfloat16_rn(a))
         | ((unsigned long long)__bfloat16_as_ushort(__float2bfloat16_rn(b)) << 16)
         | ((unsigned long long)__bfloat16_as_ushort(__float2bfloat16_rn(c)) << 32)
         | ((unsigned long long)__bfloat16_as_ushort(__float2bfloat16_rn(d)) << 48);
}
__device__ __forceinline__ float resid(float v) {
    return v - __bfloat162float(__float2bfloat16_rn(v));
}
__device__ __forceinline__ void cpasync16(uint32_t dst, const void* src) {
    asm volatile("cp.async.cg.shared.global [%0], [%1], 16;" :: "r"(dst), "l"(src) : "memory");
}
__device__ __forceinline__ void ldm_x4(uint32_t* r, uint32_t addr) {
    asm volatile("ldmatrix.sync.aligned.m8n8.x4.shared.b16 {%0,%1,%2,%3}, [%4];"
                 : "=r"(r[0]), "=r"(r[1]), "=r"(r[2]), "=r"(r[3]) : "r"(addr));
}
__device__ __forceinline__ void mma16816(float* d, const uint32_t* a, const uint32_t* b) {
    asm volatile("mma.sync.aligned.m16n8k16.row.col.f32.bf16.bf16.f32 "
                 "{%0,%1,%2,%3}, {%4,%5,%6,%7}, {%8,%9}, {%0,%1,%2,%3};"
                 : "+f"(d[0]), "+f"(d[1]), "+f"(d[2]), "+f"(d[3])
                 : "r"(a[0]), "r"(a[1]), "r"(a[2]), "r"(a[3]), "r"(b[0]), "r"(b[1]));
}

// ============================================================
// Kernel 1: fused RMS sumsq + bf16 hi/lo split of hidden
// ============================================================
__global__ __launch_bounds__(256) void split_a_kernel(const float* __restrict__ x) {
    int row = blockIdx.x;
    const float4* xr = (const float4*)(x + (size_t)row * HID);
    float sum = 0.f;
#pragma unroll
    for (int i = 0; i < 4; i++) {
        float4 v = xr[threadIdx.x + i * 256];
        sum += v.x * v.x + v.y * v.y + v.z * v.z + v.w * v.w;
        size_t off = (size_t)row * HID + (size_t)(threadIdx.x + i * 256) * 4;
        *(unsigned long long*)(g_ahi + off) = pk4(v.x, v.y, v.z, v.w);
        *(unsigned long long*)(g_alo + off) = pk4(resid(v.x), resid(v.y), resid(v.z), resid(v.w));
    }
#pragma unroll
    for (int o = 16; o; o >>= 1) sum += __shfl_xor_sync(0xffffffffu, sum, o);
    __shared__ float red[8];
    if ((threadIdx.x & 31) == 0) red[threadIdx.x >> 5] = sum;
    __syncthreads();
    if (threadIdx.x < 8) {
        float s = red[threadIdx.x];
#pragma unroll
        for (int o = 4; o; o >>= 1) s += __shfl_xor_sync(0xffu, s, o);
        if (threadIdx.x == 0)
            g_scale[row] = rsqrtf(s * (1.0f / (float)HID) + 1e-6f);
    }
}

// ============================================================
// Kernel 2: fold prew into W rows, bf16 hi/lo split
// ============================================================
__global__ __launch_bounds__(256) void split_b_kernel(const float* __restrict__ W,
                                                      const float* __restrict__ prew) {
    int row = blockIdx.x;
    const float4* wr = (const float4*)(W + (size_t)row * HID);
    const float4* pr = (const float4*)prew;
#pragma unroll
    for (int i = 0; i < 4; i++) {
        int f = threadIdx.x + i * 256;
        float4 w = wr[f], p = pr[f];
        w.x *= p.x; w.y *= p.y; w.z *= p.z; w.w *= p.w;
        size_t off = (size_t)row * HID + (size_t)f * 4;
        *(unsigned long long*)(g_bhi + off) = pk4(w.x, w.y, w.z, w.w);
        *(unsigned long long*)(g_blo + off) = pk4(resid(w.x), resid(w.y), resid(w.z), resid(w.w));
    }
}

// ============================================================
// Kernel 3: HMMA bf16x3 GEMM. M=128/CTA, N=256/CTA, K=4096 x 3 splits.
// BK=64 (128B rows, XOR-swizzled), 2-stage cp.async pipeline.
// ============================================================
#define STG 98304
#define OFF_AH 0
#define OFF_AL 16384
#define OFF_BH 32768
#define OFF_BL 65536
#define SMEM_REQ (2*STG)
#define NSTAGES 64

__global__ void __launch_bounds__(256, 1) gemm_hmma_kernel() {
    extern __shared__ __align__(16) uint8_t sm[];
    const uint32_t smb = (uint32_t)__cvta_generic_to_shared(sm);
    const int tid = threadIdx.x;
    const int lane = tid & 31;
    const int wid = tid >> 5;
    const int m0 = blockIdx.y * 128;
    const int n0 = blockIdx.x * 256;
    const int wm = (wid & 1) * 64;     // warp m-offset within CTA
    const int wn = (wid >> 1) * 64;    // warp n-offset within CTA

    float acc[4][8][4];
#pragma unroll
    for (int i = 0; i < 4; i++)
#pragma unroll
        for (int j = 0; j < 8; j++)
#pragma unroll
            for (int q = 0; q < 4; q++) acc[i][j][q] = 0.f;

    // ---------- stage loader (cp.async) ----------
    auto load_stage = [&](int s) {
        const uint32_t base = smb + (s & 1) * STG;
        const int k0 = s * 64;
        // A: 128 rows x 8 chunks, hi+lo
#pragma unroll
        for (int i = 0; i < 4; i++) {
            int idx = tid + i * 256;         // 0..1023
            int r = idx >> 3, c = idx & 7;
            uint32_t so = (uint32_t)(r * 128 + ((c ^ (r & 7)) << 4));
            size_t go = (size_t)(m0 + r) * HID + k0 + c * 8;
            cpasync16(base + OFF_AH + so, g_ahi + go);
            cpasync16(base + OFF_AL + so, g_alo + go);
        }
        // B: 256 rows x 8 chunks, hi+lo
#pragma unroll
        for (int i = 0; i < 8; i++) {
            int idx = tid + i * 256;         // 0..2047
            int r = idx >> 3, c = idx & 7;
            uint32_t so = (uint32_t)(r * 128 + ((c ^ (r & 7)) << 4));
            size_t go = (size_t)(n0 + r) * HID + k0 + c * 8;
            cpasync16(base + OFF_BH + so, g_bhi + go);
            cpasync16(base + OFF_BL + so, g_blo + go);
        }
        asm volatile("cp.async.commit_group;" ::: "memory");
    };

    load_stage(0);

    // per-lane ldmatrix address components
    const int a_row = lane & 15;          // A tile row provider
    const int a_cs  = lane >> 4;          // A chunk half (0/1)
    const int b_row = (lane & 7) + ((lane >> 4) << 3);  // B row within n16 group
    const int b_cs  = (lane >> 3) & 1;    // B chunk half
    const int sxor  = lane & 7;

    for (int s = 0; s < NSTAGES; s++) {
        if (s + 1 < NSTAGES) {
            load_stage(s + 1);
            asm volatile("cp.async.wait_group 1;" ::: "memory");
        } else {
            asm volatile("cp.async.wait_group 0;" ::: "memory");
        }
        __syncthreads();

        const uint32_t base = smb + (s & 1) * STG;
        const uint32_t ah_base = base + OFF_AH + (uint32_t)((wm + a_row) * 128);
        const uint32_t al_base = base + OFF_AL + (uint32_t)((wm + a_row) * 128);
        const uint32_t bh_base = base + OFF_BH + (uint32_t)((wn + b_row) * 128);
        const uint32_t bl_base = base + OFF_BL + (uint32_t)((wn + b_row) * 128);

#pragma unroll
        for (int kk = 0; kk < 4; kk++) {
            const uint32_t a_off = (uint32_t)(((kk * 2 + a_cs) ^ sxor) << 4);
            const uint32_t b_off = (uint32_t)(((kk * 2 + b_cs) ^ sxor) << 4);
            uint32_t ah[4][4], al[4][4];
#pragma unroll
            for (int mi = 0; mi < 4; mi++) {
                ldm_x4(ah[mi], ah_base + (uint32_t)(mi * 16 * 128) + a_off);
                ldm_x4(al[mi], al_base + (uint32_t)(mi * 16 * 128) + a_off);
            }
#pragma unroll
            for (int p = 0; p < 4; p++) {      // n16 groups (2 frags each)
                uint32_t bh[4], bl[4];
                ldm_x4(bh, bh_base + (uint32_t)(p * 16 * 128) + b_off);
                ldm_x4(bl, bl_base + (uint32_t)(p * 16 * 128) + b_off);
#pragma unroll
                for (int mi = 0; mi < 4; mi++) {
                    mma16816(acc[mi][2 * p],     ah[mi], &bh[0]);
                    mma16816(acc[mi][2 * p + 1], ah[mi], &bh[2]);
                    mma16816(acc[mi][2 * p],     ah[mi], &bl[0]);
                    mma16816(acc[mi][2 * p + 1], ah[mi], &bl[2]);
                    mma16816(acc[mi][2 * p],     al[mi], &bh[0]);
                    mma16816(acc[mi][2 * p + 1], al[mi], &bh[2]);
                }
            }
        }
        __syncthreads();
    }

    // ---------- epilogue: scale rows, write g_q ----------
#pragma unroll
    for (int mi = 0; mi < 4; mi++) {
        int r0 = m0 + wm + mi * 16 + (lane >> 2);
        float s0 = g_scale[r0], s1 = g_scale[r0 + 8];
        float* q0 = g_q + (size_t)r0 * RDIM + n0 + wn + (lane & 3) * 2;
        float* q1 = q0 + (size_t)8 * RDIM;
#pragma unroll
        for (int ni = 0; ni < 8; ni++) {
            float2 v0 = make_float2(acc[mi][ni][0] * s0, acc[mi][ni][1] * s0);
            float2 v1 = make_float2(acc[mi][ni][2] * s1, acc[mi][ni][3] * s1);
            *(float2*)(q0 + ni * 8) = v0;
            *(float2*)(q1 + ni * 8) = v1;
        }
    }
}

// ============================================================
// Kernel 4: scores + causal top-16 + weights
// ============================================================
__global__ __launch_bounds__(128) void scores_kernel(const float* __restrict__ lmk,
                                                     float* __restrict__ out) {
    const int n = blockIdx.z;
    const int h = blockIdx.y;
    const int c = blockIdx.x * 128 + threadIdx.x;

    __shared__ __align__(16) float4 sL[DD * 16];
    {
        int d = threadIdx.x;
        const float4* src = (const float4*)(lmk + ((size_t)((n * DD + d) * HH + h) << 6));
#pragma unroll
        for (int e = 0; e < 16; e++) sL[d * 16 + e] = src[e];
    }
    __syncthreads();

    float4 qv[16];
    const float4* qp = (const float4*)(g_q + ((size_t)(n * CC + c) * RDIM + h * 64));
#pragma unroll
    for (int e = 0; e < 16; e++) qv[e] = qp[e];

    int v = c >> 6;
    float tv[TOPK];
    int   ti[TOPK];
#pragma unroll
    for (int i = 0; i < TOPK; i++) { tv[i] = -INFINITY; ti[i] = -1; }

    for (int j = 0; j < v; j++) {
        float dot = 0.f;
#pragma unroll
        for (int e = 0; e < 16; e++) {
            float4 l = sL[j * 16 + e];
            dot += qv[e].x * l.x + qv[e].y * l.y + qv[e].z * l.z + qv[e].w * l.w;
        }
        float s = dot * 0.125f;
        if (s > tv[0]) {
            bool done = false;
#pragma unroll
            for (int i = 0; i < TOPK - 1; i++) {
                if (!done) {
                    if (tv[i + 1] < s) { tv[i] = tv[i + 1]; ti[i] = ti[i + 1]; }
                    else               { tv[i] = s; ti[i] = j; done = true; }
                }
            }
            if (!done) { tv[TOPK - 1] = s; ti[TOPK - 1] = j; }
        }
    }
#pragma unroll
    for (int a = 0; a < TOPK - 1; a++)
#pragma unroll
        for (int b = 0; b < TOPK - 1 - a; b++)
            if (ti[b] < ti[b + 1]) {
                int   t0 = ti[b]; ti[b] = ti[b + 1]; ti[b + 1] = t0;
                float t1 = tv[b]; tv[b] = tv[b + 1]; tv[b + 1] = t1;
            }

    const size_t IDX_OFF = (size_t)NB * CC * HH * TOPK;
    size_t base = ((size_t)(n * CC + c) * HH + h) << 4;
    float cum = 0.f;
#pragma unroll
    for (int i = 0; i < TOPK; i++) {
        bool valid = ti[i] >= 0;
        float s = valid ? tv[i] : -INFINITY;
        float sp = (s > 15.0f) ? s : log1pf(expf(s));
        cum += sp;
        out[base + i] = expf(s - cum);
        out[IDX_OFF + base + i] = valid ? (float)ti[i] : 0.0f;
    }
}

// ============================================================
extern "C" void kernel_launch(void* const* d_in, const int* in_sizes, int n_in,
                              void* d_out, int out_size) {
    const float* hidden = (const float*)d_in[0];
    const float* lmk    = (const float*)d_in[1];
    const float* prew   = (const float*)d_in[2];
    const float* W      = (const float*)d_in[3];
    float* out = (float*)d_out;

    split_a_kernel<<<NROWS, 256>>>(hidden);
    split_b_kernel<<<RDIM, 256>>>(W, prew);
    static bool attr_set = false;
    if (!attr_set) {
        cudaFuncSetAttribute(gemm_hmma_kernel,
                             cudaFuncAttributeMaxDynamicSharedMemorySize, SMEM_REQ);
        attr_set = true;
    }
    gemm_hmma_kernel<<<dim3(2, 128), 256, SMEM_REQ>>>();
    scores_kernel<<<dim3(CC / 128, HH, NB), 128>>>(lmk, out);
}